// round 1
// baseline (speedup 1.0000x reference)
#include <cuda_runtime.h>
#include <cuda_bf16.h>

// Problem shape (fixed by the reference)
constexpr int Bv = 2;
constexpr int Hn = 16;
constexpr int S  = 2048;
constexpr int D  = 64;
constexpr float SCALE = 0.125f;   // 1/sqrt(64)

// Tiling
constexpr int ROWS = 16;   // query rows per block (one per warp)
constexpr int TK   = 64;   // keys per tile
constexpr int THREADS = ROWS * 32;   // 512
constexpr int KPAD = 68;   // padded K row stride (floats) for conflict-free lane-major reads

__global__ __launch_bounds__(THREADS)
void sdpa_kernel(const float* __restrict__ Q,
                 const float* __restrict__ K,
                 const float* __restrict__ V,
                 const unsigned int* __restrict__ mask,
                 float* __restrict__ O)
{
    __shared__ float ks[TK][KPAD];   // 64 x 68 floats
    __shared__ float vs[TK][D];      // 64 x 64 floats
    __shared__ float qs[ROWS][D];    // 16 x 64 floats

    const int nqb  = S / ROWS;                 // 128 q-blocks per (b,h)
    const int bh   = blockIdx.x / nqb;         // 0..31
    const int qb   = blockIdx.x % nqb;
    const int b    = bh / Hn;

    const int tid  = threadIdx.x;
    const int warp = tid >> 5;
    const int lane = tid & 31;
    const int qrow = qb * ROWS + warp;

    // ---- load Q tile (16x64 floats = 256 float4) ----
    const float* Qbase = Q + ((size_t)bh * S + (size_t)qb * ROWS) * D;
    if (tid < (ROWS * D) / 4) {
        ((float4*)qs)[tid] = ((const float4*)Qbase)[tid];
    }

    const float*        Kbh  = K + (size_t)bh * S * D;
    const float*        Vbh  = V + (size_t)bh * S * D;
    const unsigned int* mrow = mask + ((size_t)b * S + (size_t)qrow) * S;

    float m = -1e30f, l = 0.f, acc0 = 0.f, acc1 = 0.f;

    for (int t = 0; t < S / TK; ++t) {
        __syncthreads();   // protect smem from previous iteration's readers

        // ---- load K/V tile: 64x64 floats each = 1024 float4 each ----
        {
            const float4* kg = (const float4*)(Kbh + (size_t)t * TK * D);
            const float4* vg = (const float4*)(Vbh + (size_t)t * TK * D);
            #pragma unroll
            for (int r = 0; r < 2; ++r) {
                int idx = tid + r * THREADS;   // 0..1023
                int row = idx >> 4;            // /16 float4 per row
                int c4  = idx & 15;
                float4 kv = kg[idx];
                *(float4*)&ks[row][c4 * 4] = kv;   // row base 272B: 16B aligned
                *(float4*)&vs[row][c4 * 4] = vg[idx];
            }
        }
        __syncthreads();

        // ---- QK^T for this warp's row: lane owns keys {lane, lane+32} ----
        float s0 = 0.f, s1 = 0.f;
        const float* qr = qs[warp];
        #pragma unroll
        for (int d = 0; d < D; d += 4) {
            float4 q4 = *(const float4*)&qr[d];
            float4 k0 = *(const float4*)&ks[lane][d];
            float4 k1 = *(const float4*)&ks[lane + 32][d];
            s0 = fmaf(q4.x, k0.x, s0); s0 = fmaf(q4.y, k0.y, s0);
            s0 = fmaf(q4.z, k0.z, s0); s0 = fmaf(q4.w, k0.w, s0);
            s1 = fmaf(q4.x, k1.x, s1); s1 = fmaf(q4.y, k1.y, s1);
            s1 = fmaf(q4.z, k1.z, s1); s1 = fmaf(q4.w, k1.w, s1);
        }
        s0 *= SCALE; s1 *= SCALE;

        // mask == nonzero means "masked out" -> -inf (use -1e30 to avoid inf/NaN)
        unsigned int mm0 = mrow[t * TK + lane];
        unsigned int mm1 = mrow[t * TK + lane + 32];
        if (mm0) s0 = -1e30f;
        if (mm1) s1 = -1e30f;

        // ---- online softmax ----
        float tmax = fmaxf(s0, s1);
        #pragma unroll
        for (int o = 16; o > 0; o >>= 1)
            tmax = fmaxf(tmax, __shfl_xor_sync(0xffffffffu, tmax, o));
        float mn   = fmaxf(m, tmax);
        float safe = (mn < -5e29f) ? 0.f : mn;   // all-masked-so-far guard
        float sc   = __expf(m - safe);
        acc0 *= sc; acc1 *= sc; l *= sc;

        float p0 = __expf(s0 - safe);
        float p1 = __expf(s1 - safe);
        float ps = p0 + p1;
        #pragma unroll
        for (int o = 16; o > 0; o >>= 1)
            ps += __shfl_xor_sync(0xffffffffu, ps, o);
        l += ps;
        m = mn;

        // ---- P @ V: lane owns output dims {2*lane, 2*lane+1} ----
        #pragma unroll
        for (int src = 0; src < 32; ++src) {
            float pa = __shfl_sync(0xffffffffu, p0, src);
            float pb = __shfl_sync(0xffffffffu, p1, src);
            float2 va = *(const float2*)&vs[src][2 * lane];
            float2 vb = *(const float2*)&vs[src + 32][2 * lane];
            acc0 = fmaf(pa, va.x, acc0);
            acc1 = fmaf(pa, va.y, acc1);
            acc0 = fmaf(pb, vb.x, acc0);
            acc1 = fmaf(pb, vb.y, acc1);
        }
    }

    // fully-masked row -> l == 0 -> output 0 (matches nan_to_num)
    float inv = (l > 0.f) ? (1.f / l) : 0.f;
    float2 o2 = make_float2(acc0 * inv, acc1 * inv);
    *(float2*)&O[((size_t)bh * S + (size_t)qrow) * D + 2 * lane] = o2;
}

extern "C" void kernel_launch(void* const* d_in, const int* in_sizes, int n_in,
                              void* d_out, int out_size)
{
    const float* Q = (const float*)d_in[0];
    const float* K = (const float*)d_in[1];
    const float* V = (const float*)d_in[2];
    const unsigned int* mask = (const unsigned int*)d_in[3];
    float* O = (float*)d_out;

    dim3 grid(Bv * Hn * (S / ROWS));
    dim3 block(THREADS);
    sdpa_kernel<<<grid, block>>>(Q, K, V, mask, O);
}

// round 3
// speedup vs baseline: 7.1845x; 7.1845x over previous
#include <cuda_runtime.h>
#include <cstdint>

// Problem shape
constexpr int Hn = 16, Sq = 2048, Dh = 64;
constexpr float SCALE = 0.125f;

// Tiling
constexpr int MQ = 64;            // query rows per CTA (16 per warp)
constexpr int NK = 64;            // keys per tile
constexpr int THREADS = 128;
constexpr int NITER = Sq / NK;    // 32

// smem strides (floats) — chosen for conflict-free fragment LDS
constexpr int KS_STRIDE = 68;
constexpr int VS_STRIDE = 72;
constexpr int PS_STRIDE = 68;

constexpr int KS_OFF = 0;
constexpr int VS_OFF = NK * KS_STRIDE;               // 4352 floats
constexpr int PS_OFF = VS_OFF + NK * VS_STRIDE;      // 8960 floats
constexpr int SMEM_FLOATS = PS_OFF + 4 * 16 * PS_STRIDE;   // 13312
constexpr int SMEM_BYTES = SMEM_FLOATS * 4;          // 53248

__device__ __forceinline__ float f2tf(float f) {
    uint32_t r;
    asm("cvt.rna.tf32.f32 %0, %1;" : "=r"(r) : "f"(f));
    return __uint_as_float(r);
}
__device__ __forceinline__ void mma_tf32(float* c, const uint32_t* a, uint32_t b0, uint32_t b1) {
    asm volatile(
        "mma.sync.aligned.m16n8k8.row.col.f32.tf32.tf32.f32 "
        "{%0,%1,%2,%3}, {%4,%5,%6,%7}, {%8,%9}, {%0,%1,%2,%3};"
        : "+f"(c[0]), "+f"(c[1]), "+f"(c[2]), "+f"(c[3])
        : "r"(a[0]), "r"(a[1]), "r"(a[2]), "r"(a[3]), "r"(b0), "r"(b1));
}

__global__ __launch_bounds__(THREADS, 1)
void sdpa_mma(const float* __restrict__ Q, const float* __restrict__ K,
              const float* __restrict__ V, const unsigned int* __restrict__ mask,
              float* __restrict__ O)
{
    extern __shared__ float sm[];
    float* Ks = sm + KS_OFF;
    float* Vs = sm + VS_OFF;

    const int tid  = threadIdx.x;
    const int lane = tid & 31;
    const int warp = tid >> 5;
    float* Ps = sm + PS_OFF + warp * 16 * PS_STRIDE;   // warp-private

    const int nqb = Sq / MQ;              // 32
    const int bh  = blockIdx.x / nqb;
    const int qb  = blockIdx.x % nqb;
    const int b   = bh / Hn;

    const int g  = lane >> 2;             // groupID: row within fragment
    const int tg = lane & 3;              // thread-in-group

    // ---- load this warp's 16 Q rows via Ps staging, build A fragments ----
    const float* Qw = Q + ((size_t)bh * Sq + (size_t)(qb * MQ + warp * 16)) * Dh;
    #pragma unroll
    for (int i = 0; i < 8; ++i) {
        int idx = lane + 32 * i;          // 0..255 float4s
        int r = idx >> 4, c4 = (idx & 15) * 4;
        float4 v = ((const float4*)Qw)[idx];
        float* dst = Ps + r * PS_STRIDE + c4;
        dst[0] = f2tf(v.x); dst[1] = f2tf(v.y); dst[2] = f2tf(v.z); dst[3] = f2tf(v.w);
    }
    __syncwarp();
    uint32_t qf[8][4];
    #pragma unroll
    for (int ks = 0; ks < 8; ++ks) {
        int c = ks * 8;
        qf[ks][0] = __float_as_uint(Ps[g * PS_STRIDE + c + tg]);
        qf[ks][1] = __float_as_uint(Ps[(g + 8) * PS_STRIDE + c + tg]);
        qf[ks][2] = __float_as_uint(Ps[g * PS_STRIDE + c + tg + 4]);
        qf[ks][3] = __float_as_uint(Ps[(g + 8) * PS_STRIDE + c + tg + 4]);
    }
    __syncwarp();

    const float* Kbh = K + (size_t)bh * Sq * Dh;
    const float* Vbh = V + (size_t)bh * Sq * Dh;
    const int qr0 = qb * MQ + warp * 16 + g;                  // row for c0,c1
    const unsigned int* mr0 = mask + ((size_t)b * Sq + qr0) * Sq;
    const unsigned int* mr1 = mr0 + 8 * (size_t)Sq;           // row qr0+8

    float ow[8][4];
    #pragma unroll
    for (int n = 0; n < 8; ++n)
        ow[n][0] = ow[n][1] = ow[n][2] = ow[n][3] = 0.f;
    float m0 = -1e30f, m1 = -1e30f, l0 = 0.f, l1 = 0.f;

    for (int t = 0; t < NITER; ++t) {
        __syncthreads();   // all warps done reading previous Ks/Vs

        // ---- load K,V tiles (tf32-rounded) ----
        const float4* kg = (const float4*)(Kbh + (size_t)t * NK * Dh);
        const float4* vg = (const float4*)(Vbh + (size_t)t * NK * Dh);
        #pragma unroll
        for (int i = 0; i < 8; ++i) {
            int idx = tid + i * THREADS;      // 0..1023
            int r = idx >> 4, c4 = (idx & 15) * 4;
            float4 kv = kg[idx];
            float* kd = Ks + r * KS_STRIDE + c4;
            kd[0] = f2tf(kv.x); kd[1] = f2tf(kv.y); kd[2] = f2tf(kv.z); kd[3] = f2tf(kv.w);
            float4 vv = vg[idx];
            float* vd = Vs + r * VS_STRIDE + c4;
            vd[0] = f2tf(vv.x); vd[1] = f2tf(vv.y); vd[2] = f2tf(vv.z); vd[3] = f2tf(vv.w);
        }
        __syncthreads();

        // ---- QK^T: sc[n] covers rows {g, g+8}, cols n*8 + {2tg, 2tg+1} ----
        float sc[8][4];
        #pragma unroll
        for (int n = 0; n < 8; ++n)
            sc[n][0] = sc[n][1] = sc[n][2] = sc[n][3] = 0.f;
        #pragma unroll
        for (int ks = 0; ks < 8; ++ks) {
            #pragma unroll
            for (int n = 0; n < 8; ++n) {
                const float* kr = Ks + (n * 8 + g) * KS_STRIDE + ks * 8 + tg;
                uint32_t b0 = __float_as_uint(kr[0]);
                uint32_t b1 = __float_as_uint(kr[4]);
                mma_tf32(sc[n], qf[ks], b0, b1);
            }
        }

        // ---- scale + mask ----
        float tm0 = -1e30f, tm1 = -1e30f;
        #pragma unroll
        for (int n = 0; n < 8; ++n) {
            int col = t * NK + n * 8 + 2 * tg;
            uint2 mm0 = *(const uint2*)(mr0 + col);
            uint2 mm1 = *(const uint2*)(mr1 + col);
            float s0 = sc[n][0] * SCALE; if (mm0.x) s0 = -1e30f;
            float s1 = sc[n][1] * SCALE; if (mm0.y) s1 = -1e30f;
            float s2 = sc[n][2] * SCALE; if (mm1.x) s2 = -1e30f;
            float s3 = sc[n][3] * SCALE; if (mm1.y) s3 = -1e30f;
            sc[n][0] = s0; sc[n][1] = s1; sc[n][2] = s2; sc[n][3] = s3;
            tm0 = fmaxf(tm0, fmaxf(s0, s1));
            tm1 = fmaxf(tm1, fmaxf(s2, s3));
        }
        // row-max across the 4 lanes sharing each row
        tm0 = fmaxf(tm0, __shfl_xor_sync(0xffffffffu, tm0, 1));
        tm0 = fmaxf(tm0, __shfl_xor_sync(0xffffffffu, tm0, 2));
        tm1 = fmaxf(tm1, __shfl_xor_sync(0xffffffffu, tm1, 1));
        tm1 = fmaxf(tm1, __shfl_xor_sync(0xffffffffu, tm1, 2));

        float mn0 = fmaxf(m0, tm0), mn1 = fmaxf(m1, tm1);
        float sf0 = (mn0 < -5e29f) ? 0.f : mn0;
        float sf1 = (mn1 < -5e29f) ? 0.f : mn1;
        float c0 = __expf(m0 - sf0), c1 = __expf(m1 - sf1);
        l0 *= c0; l1 *= c1; m0 = mn0; m1 = mn1;

        // ---- exp, accumulate l, stage P (tf32) in warp-private smem ----
        float ps0 = 0.f, ps1 = 0.f;
        #pragma unroll
        for (int n = 0; n < 8; ++n) {
            float p0 = __expf(sc[n][0] - sf0);
            float p1 = __expf(sc[n][1] - sf0);
            float p2 = __expf(sc[n][2] - sf1);
            float p3 = __expf(sc[n][3] - sf1);
            ps0 += p0 + p1; ps1 += p2 + p3;
            int col = n * 8 + 2 * tg;
            *(float2*)(Ps + g * PS_STRIDE + col)       = make_float2(f2tf(p0), f2tf(p1));
            *(float2*)(Ps + (g + 8) * PS_STRIDE + col) = make_float2(f2tf(p2), f2tf(p3));
            ow[n][0] *= c0; ow[n][1] *= c0; ow[n][2] *= c1; ow[n][3] *= c1;
        }
        ps0 += __shfl_xor_sync(0xffffffffu, ps0, 1);
        ps0 += __shfl_xor_sync(0xffffffffu, ps0, 2);
        ps1 += __shfl_xor_sync(0xffffffffu, ps1, 1);
        ps1 += __shfl_xor_sync(0xffffffffu, ps1, 2);
        l0 += ps0; l1 += ps1;
        __syncwarp();

        // ---- PV: O += P @ V ----
        #pragma unroll
        for (int ks = 0; ks < 8; ++ks) {
            uint32_t af[4];
            const float* pr = Ps + g * PS_STRIDE + ks * 8 + tg;
            af[0] = __float_as_uint(pr[0]);
            af[2] = __float_as_uint(pr[4]);
            const float* pr1 = pr + 8 * PS_STRIDE;
            af[1] = __float_as_uint(pr1[0]);
            af[3] = __float_as_uint(pr1[4]);
            #pragma unroll
            for (int n = 0; n < 8; ++n) {
                const float* vr = Vs + (ks * 8 + tg) * VS_STRIDE + n * 8 + g;
                uint32_t b0 = __float_as_uint(vr[0]);
                uint32_t b1 = __float_as_uint(vr[4 * VS_STRIDE]);
                mma_tf32(ow[n], af, b0, b1);
            }
        }
        __syncwarp();   // P reads done before next-iter P writes
    }

    // ---- epilogue ----
    float inv0 = (l0 > 0.f) ? (1.f / l0) : 0.f;
    float inv1 = (l1 > 0.f) ? (1.f / l1) : 0.f;
    float* Ob = O + ((size_t)bh * Sq + (size_t)(qb * MQ + warp * 16)) * Dh;
    #pragma unroll
    for (int n = 0; n < 8; ++n) {
        int col = n * 8 + 2 * tg;
        *(float2*)&Ob[g * Dh + col]       = make_float2(ow[n][0] * inv0, ow[n][1] * inv0);
        *(float2*)&Ob[(g + 8) * Dh + col] = make_float2(ow[n][2] * inv1, ow[n][3] * inv1);
    }
}

extern "C" void kernel_launch(void* const* d_in, const int* in_sizes, int n_in,
                              void* d_out, int out_size)
{
    const float* Q = (const float*)d_in[0];
    const float* K = (const float*)d_in[1];
    const float* V = (const float*)d_in[2];
    const unsigned int* mask = (const unsigned int*)d_in[3];
    float* O = (float*)d_out;

    cudaFuncSetAttribute(sdpa_mma, cudaFuncAttributeMaxDynamicSharedMemorySize, SMEM_BYTES);
    dim3 grid(2 * Hn * (Sq / MQ));   // 1024
    sdpa_mma<<<grid, THREADS, SMEM_BYTES>>>(Q, K, V, mask, O);
}

// round 4
// speedup vs baseline: 8.2990x; 1.1551x over previous
#include <cuda_runtime.h>
#include <cstdint>

// Problem shape
constexpr int Hn = 16, Sq = 2048, Dh = 64;
constexpr float SCALE = 0.125f;

// Tiling: CTA = 128 q-rows, 4 warps x 32 rows; 64-key tiles, double-buffered
constexpr int MQ = 128, NK = 64, THREADS = 128;
constexpr int NITER = Sq / NK;                    // 32

// smem strides (floats / bytes)
constexpr int QSF = 68, KSF = 68, VSF = 72;
constexpr int QROW = QSF * 4, KROW = KSF * 4, VROW = VSF * 4;   // 272/272/288
constexpr int Q_OFF = 0;
constexpr int KBUF  = NK * KROW;                  // 17408
constexpr int K_OFF = Q_OFF + MQ * QROW;          // 34816
constexpr int VBUF  = NK * VROW;                  // 18432
constexpr int V_OFF = K_OFF + 2 * KBUF;           // 69632
constexpr int SMEM_BYTES = V_OFF + 2 * VBUF;      // 106496

__device__ __forceinline__ uint32_t smem_u32(const void* p) {
    uint32_t a;
    asm("{ .reg .u64 t; cvta.to.shared.u64 t, %1; cvt.u32.u64 %0, t; }" : "=r"(a) : "l"(p));
    return a;
}
__device__ __forceinline__ uint32_t f2tf(float f) {
    uint32_t r;
    asm("cvt.rna.tf32.f32 %0, %1;" : "=r"(r) : "f"(f));
    return r;
}
__device__ __forceinline__ void cp16(uint32_t dst, const void* src) {
    asm volatile("cp.async.cg.shared.global [%0], [%1], 16;" :: "r"(dst), "l"(src));
}
__device__ __forceinline__ void mma_tf32(float* c, const uint32_t* a, uint32_t b0, uint32_t b1) {
    asm volatile(
        "mma.sync.aligned.m16n8k8.row.col.f32.tf32.tf32.f32 "
        "{%0,%1,%2,%3}, {%4,%5,%6,%7}, {%8,%9}, {%0,%1,%2,%3};"
        : "+f"(c[0]), "+f"(c[1]), "+f"(c[2]), "+f"(c[3])
        : "r"(a[0]), "r"(a[1]), "r"(a[2]), "r"(a[3]), "r"(b0), "r"(b1));
}

__global__ __launch_bounds__(THREADS)
void sdpa_mma2(const float* __restrict__ Q, const float* __restrict__ K,
               const float* __restrict__ V, const unsigned int* __restrict__ mask,
               float* __restrict__ O)
{
    extern __shared__ char smc[];
    const uint32_t sb = smem_u32(smc);

    const int tid  = threadIdx.x;
    const int lane = tid & 31;
    const int warp = tid >> 5;
    const int g    = lane >> 2;
    const int tg   = lane & 3;

    const int nqb = Sq / MQ;                 // 16
    const int bh  = blockIdx.x / nqb;
    const int qb  = blockIdx.x % nqb;
    const int b   = bh / Hn;

    const float* Kbh = K + (size_t)bh * Sq * Dh;
    const float* Vbh = V + (size_t)bh * Sq * Dh;

    // ---- cp.async prefetch of K/V tile t into buffer bi (V rows pair-permuted) ----
    auto prefetch = [&](int t, int bi) {
        const float* ksrc = Kbh + (size_t)t * NK * Dh;
        const float* vsrc = Vbh + (size_t)t * NK * Dh;
        #pragma unroll
        for (int i = 0; i < 8; ++i) {
            int idx = tid + i * THREADS;     // 0..1023
            int r = idx >> 4, c = idx & 15;
            cp16(sb + K_OFF + bi * KBUF + r * KROW + c * 16, ksrc + r * Dh + c * 4);
            int rp = (r & 0x38) | ((r & 1) << 2) | ((r & 7) >> 1);
            cp16(sb + V_OFF + bi * VBUF + rp * VROW + c * 16, vsrc + r * Dh + c * 4);
        }
    };
    prefetch(0, 0); asm volatile("cp.async.commit_group;");
    prefetch(1, 1); asm volatile("cp.async.commit_group;");

    // ---- stage Q (pre-converted tf32) into smem ----
    {
        const float4* qg = (const float4*)(Q + ((size_t)bh * Sq + (size_t)qb * MQ) * Dh);
        #pragma unroll
        for (int i = 0; i < 16; ++i) {
            int idx = tid + i * THREADS;     // 0..2047
            int r = idx >> 4, c4 = idx & 15;
            float4 v = qg[idx];
            uint4 u = make_uint4(f2tf(v.x), f2tf(v.y), f2tf(v.z), f2tf(v.w));
            *(uint4*)(smc + Q_OFF + r * QROW + c4 * 16) = u;
        }
    }

    // mask row pointers: this thread covers rows qbase + g + 8*j, j=0..3
    const int qbase = qb * MQ + warp * 32 + g;
    const unsigned int* mr[4];
    #pragma unroll
    for (int j = 0; j < 4; ++j)
        mr[j] = mask + ((size_t)b * Sq + (size_t)(qbase + 8 * j)) * Sq;

    float ow[2][8][4];
    #pragma unroll
    for (int gp = 0; gp < 2; ++gp)
        #pragma unroll
        for (int n = 0; n < 8; ++n)
            ow[gp][n][0] = ow[gp][n][1] = ow[gp][n][2] = ow[gp][n][3] = 0.f;
    float mrw[4] = {-1e30f, -1e30f, -1e30f, -1e30f};
    float lrw[4] = {0.f, 0.f, 0.f, 0.f};

    const uint32_t* Qw = (const uint32_t*)(smc + Q_OFF) + (warp * 32) * QSF;

    for (int t = 0; t < NITER; ++t) {
        const int bi = t & 1;
        asm volatile("cp.async.wait_group 1;" ::: "memory");
        __syncthreads();

        const float* Kb = (const float*)(smc + K_OFF + bi * KBUF);
        const float* Vb = (const float*)(smc + V_OFF + bi * VBUF);

        // ---- QK^T ----
        float sc[2][8][4];
        #pragma unroll
        for (int gp = 0; gp < 2; ++gp)
            #pragma unroll
            for (int n = 0; n < 8; ++n)
                sc[gp][n][0] = sc[gp][n][1] = sc[gp][n][2] = sc[gp][n][3] = 0.f;

        #pragma unroll
        for (int ks = 0; ks < 8; ++ks) {
            const int col = ks * 8 + tg;
            uint32_t a0[4], a1[4];
            a0[0] = Qw[(g     ) * QSF + col];
            a0[1] = Qw[(g +  8) * QSF + col];
            a0[2] = Qw[(g     ) * QSF + col + 4];
            a0[3] = Qw[(g +  8) * QSF + col + 4];
            a1[0] = Qw[(g + 16) * QSF + col];
            a1[1] = Qw[(g + 24) * QSF + col];
            a1[2] = Qw[(g + 16) * QSF + col + 4];
            a1[3] = Qw[(g + 24) * QSF + col + 4];
            #pragma unroll
            for (int n = 0; n < 8; ++n) {
                const float* kr = Kb + (n * 8 + g) * KSF + col;
                uint32_t kb0 = f2tf(kr[0]);
                uint32_t kb1 = f2tf(kr[4]);
                mma_tf32(sc[0][n], a0, kb0, kb1);
                mma_tf32(sc[1][n], a1, kb0, kb1);
            }
        }

        // ---- scale + mask + row maxima ----
        float tmax[4] = {-1e30f, -1e30f, -1e30f, -1e30f};
        #pragma unroll
        for (int gp = 0; gp < 2; ++gp) {
            #pragma unroll
            for (int n = 0; n < 8; ++n) {
                int col = t * NK + n * 8 + 2 * tg;
                uint2 m0 = *(const uint2*)(mr[2 * gp]     + col);
                uint2 m1 = *(const uint2*)(mr[2 * gp + 1] + col);
                float s0 = sc[gp][n][0] * SCALE; if (m0.x) s0 = -1e30f;
                float s1 = sc[gp][n][1] * SCALE; if (m0.y) s1 = -1e30f;
                float s2 = sc[gp][n][2] * SCALE; if (m1.x) s2 = -1e30f;
                float s3 = sc[gp][n][3] * SCALE; if (m1.y) s3 = -1e30f;
                sc[gp][n][0] = s0; sc[gp][n][1] = s1;
                sc[gp][n][2] = s2; sc[gp][n][3] = s3;
                tmax[2 * gp]     = fmaxf(tmax[2 * gp],     fmaxf(s0, s1));
                tmax[2 * gp + 1] = fmaxf(tmax[2 * gp + 1], fmaxf(s2, s3));
            }
        }
        #pragma unroll
        for (int j = 0; j < 4; ++j) {
            tmax[j] = fmaxf(tmax[j], __shfl_xor_sync(0xffffffffu, tmax[j], 1));
            tmax[j] = fmaxf(tmax[j], __shfl_xor_sync(0xffffffffu, tmax[j], 2));
        }

        float sf[4], corr[4];
        #pragma unroll
        for (int j = 0; j < 4; ++j) {
            float mn = fmaxf(mrw[j], tmax[j]);
            sf[j]   = (mn < -5e29f) ? 0.f : mn;
            corr[j] = __expf(mrw[j] - sf[j]);
            lrw[j] *= corr[j];
            mrw[j]  = mn;
        }
        #pragma unroll
        for (int gp = 0; gp < 2; ++gp)
            #pragma unroll
            for (int n = 0; n < 8; ++n) {
                ow[gp][n][0] *= corr[2 * gp];     ow[gp][n][1] *= corr[2 * gp];
                ow[gp][n][2] *= corr[2 * gp + 1]; ow[gp][n][3] *= corr[2 * gp + 1];
            }

        // ---- exp; P stays in C-fragment registers ----
        float ps[4] = {0.f, 0.f, 0.f, 0.f};
        #pragma unroll
        for (int gp = 0; gp < 2; ++gp) {
            #pragma unroll
            for (int n = 0; n < 8; ++n) {
                float p0 = __expf(sc[gp][n][0] - sf[2 * gp]);
                float p1 = __expf(sc[gp][n][1] - sf[2 * gp]);
                float p2 = __expf(sc[gp][n][2] - sf[2 * gp + 1]);
                float p3 = __expf(sc[gp][n][3] - sf[2 * gp + 1]);
                sc[gp][n][0] = p0; sc[gp][n][1] = p1;
                sc[gp][n][2] = p2; sc[gp][n][3] = p3;
                ps[2 * gp] += p0 + p1; ps[2 * gp + 1] += p2 + p3;
            }
        }
        #pragma unroll
        for (int j = 0; j < 4; ++j) {
            ps[j] += __shfl_xor_sync(0xffffffffu, ps[j], 1);
            ps[j] += __shfl_xor_sync(0xffffffffu, ps[j], 2);
            lrw[j] += ps[j];
        }

        // ---- PV: V rows pair-permuted so A-frag(P) == C-frag(sc): {c0,c2,c1,c3} ----
        #pragma unroll
        for (int ks = 0; ks < 8; ++ks) {
            uint32_t af0[4] = { f2tf(sc[0][ks][0]), f2tf(sc[0][ks][2]),
                                f2tf(sc[0][ks][1]), f2tf(sc[0][ks][3]) };
            uint32_t af1[4] = { f2tf(sc[1][ks][0]), f2tf(sc[1][ks][2]),
                                f2tf(sc[1][ks][1]), f2tf(sc[1][ks][3]) };
            #pragma unroll
            for (int n = 0; n < 8; ++n) {
                const float* vr = Vb + (ks * 8 + tg) * VSF + n * 8 + g;
                uint32_t vb0 = f2tf(vr[0]);
                uint32_t vb1 = f2tf(vr[4 * VSF]);
                mma_tf32(ow[0][n], af0, vb0, vb1);
                mma_tf32(ow[1][n], af1, vb0, vb1);
            }
        }

        __syncthreads();                       // everyone done reading buf bi
        if (t + 2 < NITER) prefetch(t + 2, bi);
        asm volatile("cp.async.commit_group;");  // dummy-safe: keeps group count in sync
    }

    // ---- epilogue ----
    float inv[4];
    #pragma unroll
    for (int j = 0; j < 4; ++j) inv[j] = (lrw[j] > 0.f) ? (1.f / lrw[j]) : 0.f;

    float* Ob = O + ((size_t)bh * Sq + (size_t)(qb * MQ + warp * 32)) * Dh;
    #pragma unroll
    for (int gp = 0; gp < 2; ++gp) {
        #pragma unroll
        for (int n = 0; n < 8; ++n) {
            int col = n * 8 + 2 * tg;
            *(float2*)&Ob[(g + 16 * gp) * Dh + col] =
                make_float2(ow[gp][n][0] * inv[2 * gp], ow[gp][n][1] * inv[2 * gp]);
            *(float2*)&Ob[(g + 16 * gp + 8) * Dh + col] =
                make_float2(ow[gp][n][2] * inv[2 * gp + 1], ow[gp][n][3] * inv[2 * gp + 1]);
        }
    }
}

extern "C" void kernel_launch(void* const* d_in, const int* in_sizes, int n_in,
                              void* d_out, int out_size)
{
    const float* Q = (const float*)d_in[0];
    const float* K = (const float*)d_in[1];
    const float* V = (const float*)d_in[2];
    const unsigned int* mask = (const unsigned int*)d_in[3];
    float* O = (float*)d_out;

    cudaFuncSetAttribute(sdpa_mma2, cudaFuncAttributeMaxDynamicSharedMemorySize, SMEM_BYTES);
    dim3 grid(2 * Hn * (Sq / MQ));   // 512
    sdpa_mma2<<<grid, THREADS, SMEM_BYTES>>>(Q, K, V, mask, O);
}